// round 1
// baseline (speedup 1.0000x reference)
#include <cuda_runtime.h>
#include <cuda_bf16.h>
#include <cstdint>
#include <math.h>

// Problem dims (fixed by setup_inputs)
#define TNUM 4096
#define DDIM 1024
#define HDIM 4096
#define ODIM 1024
#define ENUM 8
#define NROWS (TNUM * 2)   // top-2 -> 8192 permuted rows total

// ---------------- scratch (static __device__, no allocs) ----------------
__device__ int   g_counts[ENUM];
__device__ int   g_offsets[ENUM];
__device__ int   g_e[NROWS];
__device__ int   g_pos[NROWS];
__device__ float g_gate[NROWS];
__device__ int   g_row_token[NROWS];   // permuted row -> source token
__device__ int   g_token_rows[NROWS];  // token*2+k -> permuted row
__device__ float g_h[(size_t)NROWS * HDIM];  // 128 MB fp32 intermediate
__device__ float g_y[(size_t)NROWS * ODIM];  // 32 MB expert outputs

// ---------------- router ----------------
__global__ void zero_counts_kernel() {
    if (threadIdx.x < ENUM) g_counts[threadIdx.x] = 0;
}

__global__ void router_kernel(const float* __restrict__ x,
                              const float* __restrict__ Wr,
                              const float* __restrict__ br) {
    int warp = threadIdx.x >> 5;
    int lane = threadIdx.x & 31;
    int t = blockIdx.x * 8 + warp;
    if (t >= TNUM) return;
    const float* xr = x + (size_t)t * DDIM;

    float acc[ENUM];
#pragma unroll
    for (int e = 0; e < ENUM; e++) acc[e] = 0.f;
    for (int d = lane; d < DDIM; d += 32) {
        float xv = xr[d];
        const float* w = Wr + (size_t)d * ENUM;
#pragma unroll
        for (int e = 0; e < ENUM; e++) acc[e] = fmaf(xv, w[e], acc[e]);
    }
#pragma unroll
    for (int e = 0; e < ENUM; e++) {
#pragma unroll
        for (int s = 16; s > 0; s >>= 1)
            acc[e] += __shfl_xor_sync(0xffffffffu, acc[e], s);
    }
    if (lane == 0) {
        float v[ENUM];
#pragma unroll
        for (int e = 0; e < ENUM; e++) v[e] = acc[e] + br[e];
        int i0 = 0; float v0 = v[0];
#pragma unroll
        for (int e = 1; e < ENUM; e++) if (v[e] > v0) { v0 = v[e]; i0 = e; }
        int i1 = -1; float v1 = -1e30f;
#pragma unroll
        for (int e = 0; e < ENUM; e++)
            if (e != i0 && v[e] > v1) { v1 = v[e]; i1 = e; }
        // softmax over the two selected logits (v0 >= v1)
        float g0 = 1.f / (1.f + expf(v1 - v0));
        float g1 = 1.f - g0;
        int p0 = atomicAdd(&g_counts[i0], 1);
        int p1 = atomicAdd(&g_counts[i1], 1);
        g_e[2 * t]     = i0; g_pos[2 * t]     = p0; g_gate[2 * t]     = g0;
        g_e[2 * t + 1] = i1; g_pos[2 * t + 1] = p1; g_gate[2 * t + 1] = g1;
    }
}

__global__ void offsets_kernel() {
    if (threadIdx.x == 0) {
        int s = 0;
        for (int e = 0; e < ENUM; e++) { g_offsets[e] = s; s += g_counts[e]; }
    }
}

__global__ void build_rows_kernel() {
    int t = blockIdx.x * blockDim.x + threadIdx.x;
    if (t >= TNUM) return;
#pragma unroll
    for (int k = 0; k < 2; k++) {
        int e = g_e[2 * t + k];
        int row = g_offsets[e] + g_pos[2 * t + k];
        g_row_token[row] = t;
        g_token_rows[2 * t + k] = row;
    }
}

// ---------------- grouped GEMM (tf32 mma.sync) ----------------
#define BM 128
#define BN 128
#define BK 32
#define SA_STRIDE 36    // BK + 4 pad  -> conflict-free A frags
#define SB_STRIDE 136   // BN + 8 pad  -> conflict-free B frags & stores

__device__ __forceinline__ unsigned f2tf32(float f) {
    unsigned u;
    asm("cvt.rna.tf32.f32 %0, %1;" : "=r"(u) : "f"(f));
    return u;
}

// PHASE 1: A = x gathered by row->token, C = g_h, ReLU+bias
// PHASE 2: A = g_h direct rows,          C = g_y, bias
template <int PHASE>
__global__ void __launch_bounds__(256, 1) moe_gemm_kernel(
    const float* __restrict__ X,      // x (only used in PHASE 1)
    const float* __restrict__ Bw,     // stacked weights [E, Kdim, Ndim]
    const float* __restrict__ biasB,  // [E, Ndim]
    int Kdim, int Ndim) {
    int e = blockIdx.z;
    int cnt = g_counts[e];
    int m0 = blockIdx.y * BM;
    if (m0 >= cnt) return;
    int rbase = g_offsets[e] + m0;
    int n0 = blockIdx.x * BN;

    __shared__ float    sA[BM * SA_STRIDE];
    __shared__ float    sB[BK * SB_STRIDE];
    __shared__ unsigned sArow[BM];   // element offset of each A row

    const float* Abase = (PHASE == 1) ? X : g_h;
    float*       Cbase = (PHASE == 1) ? g_h : g_y;
    int lda = Kdim;  // D for phase1, H for phase2

    int tid  = threadIdx.x;
    int lane = tid & 31;
    int warp = tid >> 5;
    int wm = (warp >> 2) * 64;  // warp tile 64x32 within 128x128
    int wn = (warp & 3) * 32;
    int g  = lane >> 2;         // groupID 0..7
    int tg = lane & 3;          // thread-in-group 0..3

    if (tid < BM) {
        unsigned off = 0;
        if (m0 + tid < cnt) {
            int row = rbase + tid;
            off = (PHASE == 1) ? (unsigned)(g_row_token[row] * lda)
                               : (unsigned)(row * lda);
        }
        sArow[tid] = off;
    }
    __syncthreads();

    const float* Bm = Bw + (size_t)e * Kdim * Ndim + n0;

    float acc[4][4][4];
#pragma unroll
    for (int i = 0; i < 4; i++)
#pragma unroll
        for (int j = 0; j < 4; j++)
#pragma unroll
            for (int r = 0; r < 4; r++) acc[i][j][r] = 0.f;

    float4 ra[4], rb[4];
    int a_col = (tid & 7) * 4;   // A tile: 8 float4 per 32-wide row
    int b_col = (tid & 31) * 4;  // B tile: 32 float4 per 128-wide row

    // prologue loads for k-tile 0
#pragma unroll
    for (int i = 0; i < 4; i++) {
        int r = (tid >> 3) + i * 32;
        ra[i] = *(const float4*)(Abase + (size_t)sArow[r] + 0 + a_col);
    }
#pragma unroll
    for (int i = 0; i < 4; i++) {
        int r = (tid >> 5) + i * 8;
        rb[i] = *(const float4*)(Bm + (size_t)r * Ndim + b_col);
    }

    int nk = Kdim / BK;
    for (int kt = 0; kt < nk; kt++) {
        __syncthreads();
        // store staged tile (tf32-rounded) into smem
#pragma unroll
        for (int i = 0; i < 4; i++) {
            int r = (tid >> 3) + i * 32;
            float* p = &sA[r * SA_STRIDE + a_col];
            p[0] = __uint_as_float(f2tf32(ra[i].x));
            p[1] = __uint_as_float(f2tf32(ra[i].y));
            p[2] = __uint_as_float(f2tf32(ra[i].z));
            p[3] = __uint_as_float(f2tf32(ra[i].w));
        }
#pragma unroll
        for (int i = 0; i < 4; i++) {
            int r = (tid >> 5) + i * 8;
            float* p = &sB[r * SB_STRIDE + b_col];
            p[0] = __uint_as_float(f2tf32(rb[i].x));
            p[1] = __uint_as_float(f2tf32(rb[i].y));
            p[2] = __uint_as_float(f2tf32(rb[i].z));
            p[3] = __uint_as_float(f2tf32(rb[i].w));
        }
        __syncthreads();

        // prefetch next k-tile into regs while we compute
        if (kt + 1 < nk) {
            int k0 = (kt + 1) * BK;
#pragma unroll
            for (int i = 0; i < 4; i++) {
                int r = (tid >> 3) + i * 32;
                ra[i] = *(const float4*)(Abase + (size_t)sArow[r] + k0 + a_col);
            }
#pragma unroll
            for (int i = 0; i < 4; i++) {
                int r = (tid >> 5) + i * 8;
                rb[i] = *(const float4*)(Bm + (size_t)(k0 + r) * Ndim + b_col);
            }
        }

#pragma unroll
        for (int ks = 0; ks < 4; ks++) {
            int kk = ks * 8;
            unsigned af[4][4];
#pragma unroll
            for (int i = 0; i < 4; i++) {
                int mrow = wm + i * 16;
                af[i][0] = __float_as_uint(sA[(mrow + g) * SA_STRIDE + kk + tg]);
                af[i][1] = __float_as_uint(sA[(mrow + g + 8) * SA_STRIDE + kk + tg]);
                af[i][2] = __float_as_uint(sA[(mrow + g) * SA_STRIDE + kk + tg + 4]);
                af[i][3] = __float_as_uint(sA[(mrow + g + 8) * SA_STRIDE + kk + tg + 4]);
            }
            unsigned bf[4][2];
#pragma unroll
            for (int j = 0; j < 4; j++) {
                int nc = wn + j * 8 + g;
                bf[j][0] = __float_as_uint(sB[(kk + tg) * SB_STRIDE + nc]);
                bf[j][1] = __float_as_uint(sB[(kk + tg + 4) * SB_STRIDE + nc]);
            }
#pragma unroll
            for (int i = 0; i < 4; i++)
#pragma unroll
                for (int j = 0; j < 4; j++) {
                    asm volatile(
                        "mma.sync.aligned.m16n8k8.row.col.f32.tf32.tf32.f32 "
                        "{%0,%1,%2,%3}, {%4,%5,%6,%7}, {%8,%9}, {%0,%1,%2,%3};\n"
                        : "+f"(acc[i][j][0]), "+f"(acc[i][j][1]),
                          "+f"(acc[i][j][2]), "+f"(acc[i][j][3])
                        : "r"(af[i][0]), "r"(af[i][1]), "r"(af[i][2]), "r"(af[i][3]),
                          "r"(bf[j][0]), "r"(bf[j][1]));
                }
        }
    }

    // epilogue: bias (+ReLU for phase1), masked rows
    const float* bias = biasB + (size_t)e * Ndim + n0;
#pragma unroll
    for (int i = 0; i < 4; i++) {
#pragma unroll
        for (int half = 0; half < 2; half++) {
            int ml = wm + i * 16 + g + half * 8;
            if (m0 + ml < cnt) {
                int grow = rbase + ml;
                float* crow = Cbase + (size_t)grow * Ndim + n0;
#pragma unroll
                for (int j = 0; j < 4; j++) {
                    int nc = wn + j * 8 + tg * 2;
                    float c0 = acc[i][j][half * 2 + 0] + bias[nc];
                    float c1 = acc[i][j][half * 2 + 1] + bias[nc + 1];
                    if (PHASE == 1) { c0 = fmaxf(c0, 0.f); c1 = fmaxf(c1, 0.f); }
                    float2 v; v.x = c0; v.y = c1;
                    *(float2*)(crow + nc) = v;
                }
            }
        }
    }
}

// ---------------- gated combine (deterministic, no atomics) ----------------
__global__ void combine_kernel(float* __restrict__ out) {
    int idx = blockIdx.x * blockDim.x + threadIdx.x;  // over TNUM * (ODIM/4)
    int t = idx >> 8;            // ODIM/4 = 256
    int c = (idx & 255) * 4;
    int r0 = g_token_rows[2 * t];
    int r1 = g_token_rows[2 * t + 1];
    float w0 = g_gate[2 * t];
    float w1 = g_gate[2 * t + 1];
    float4 a = *(const float4*)(g_y + (size_t)r0 * ODIM + c);
    float4 b = *(const float4*)(g_y + (size_t)r1 * ODIM + c);
    float4 o;
    o.x = w0 * a.x + w1 * b.x;
    o.y = w0 * a.y + w1 * b.y;
    o.z = w0 * a.z + w1 * b.z;
    o.w = w0 * a.w + w1 * b.w;
    *(float4*)(out + (size_t)t * ODIM + c) = o;
}

// ---------------- launch ----------------
extern "C" void kernel_launch(void* const* d_in, const int* in_sizes, int n_in,
                              void* d_out, int out_size) {
    const float* x  = (const float*)d_in[0];
    const float* Wr = (const float*)d_in[1];
    const float* br = (const float*)d_in[2];
    const float* W1 = (const float*)d_in[3];
    const float* b1 = (const float*)d_in[4];
    const float* W2 = (const float*)d_in[5];
    const float* b2 = (const float*)d_in[6];
    float* out = (float*)d_out;

    zero_counts_kernel<<<1, 32>>>();
    router_kernel<<<TNUM / 8, 256>>>(x, Wr, br);
    offsets_kernel<<<1, 32>>>();
    build_rows_kernel<<<TNUM / 256, 256>>>();

    dim3 g1(HDIM / BN, TNUM / BM, ENUM);  // 32 x 32 x 8, most tiles early-exit
    moe_gemm_kernel<1><<<g1, 256>>>(x, W1, b1, DDIM, HDIM);

    dim3 g2(ODIM / BN, TNUM / BM, ENUM);  // 8 x 32 x 8
    moe_gemm_kernel<2><<<g2, 256>>>(x, W2, b2, HDIM, ODIM);

    combine_kernel<<<TNUM, 256>>>(out);
}

// round 5
// speedup vs baseline: 1.7494x; 1.7494x over previous
#include <cuda_runtime.h>
#include <cstdint>
#include <math.h>

// Problem dims (fixed by setup_inputs)
#define TNUM 4096
#define DDIM 1024
#define HDIM 4096
#define ODIM 1024
#define ENUM 8
#define NROWS (TNUM * 2)

// ---------------- scratch (static __device__, no allocs) ----------------
// NOTE: these are ONLY referenced from device code. Passing them as kernel
// arguments from host code silently passes the host shadow symbol (R3/R4 bug).
__device__ int   g_counts[ENUM];
__device__ int   g_offsets[ENUM];
__device__ int   g_e[NROWS];
__device__ int   g_pos[NROWS];
__device__ float g_gate[NROWS];
__device__ int   g_row_token[NROWS];
__device__ int   g_token_rows[NROWS];
__device__ float g_xr[(size_t)TNUM * DDIM];   // x rounded to tf32 (16 MB)
__device__ float g_h[(size_t)NROWS * HDIM];   // tf32-rounded intermediate (128 MB)
__device__ float g_y[(size_t)NROWS * ODIM];   // expert outputs (32 MB)

__device__ __forceinline__ float rna_tf32(float f) {
    uint32_t u;
    asm("cvt.rna.tf32.f32 %0, %1;" : "=r"(u) : "f"(f));
    return __uint_as_float(u);
}
__device__ __forceinline__ uint32_t rna_tf32_u(float f) {
    uint32_t u;
    asm("cvt.rna.tf32.f32 %0, %1;" : "=r"(u) : "f"(f));
    return u;
}
__device__ __forceinline__ uint32_t smem_u32(const void* p) {
    uint32_t a;
    asm("{ .reg .u64 t; cvta.to.shared.u64 t, %1; cvt.u32.u64 %0, t; }" : "=r"(a) : "l"(p));
    return a;
}

// ---------------- prep: rounded x ----------------
__global__ void round_x_kernel(const float* __restrict__ x) {
    int i = blockIdx.x * blockDim.x + threadIdx.x;   // over TNUM*DDIM/4
    float4 v = *(const float4*)(x + (size_t)i * 4);
    v.x = rna_tf32(v.x); v.y = rna_tf32(v.y); v.z = rna_tf32(v.z); v.w = rna_tf32(v.w);
    *(float4*)(g_xr + (size_t)i * 4) = v;
}

// ---------------- router ----------------
__global__ void zero_counts_kernel() {
    if (threadIdx.x < ENUM) g_counts[threadIdx.x] = 0;
}

__global__ void router_kernel(const float* __restrict__ x,
                              const float* __restrict__ Wr,
                              const float* __restrict__ br) {
    int warp = threadIdx.x >> 5;
    int lane = threadIdx.x & 31;
    int t = blockIdx.x * 8 + warp;
    if (t >= TNUM) return;
    const float* xr = x + (size_t)t * DDIM;
    float acc[ENUM];
#pragma unroll
    for (int e = 0; e < ENUM; e++) acc[e] = 0.f;
    for (int d = lane; d < DDIM; d += 32) {
        float xv = xr[d];
        const float* w = Wr + (size_t)d * ENUM;
#pragma unroll
        for (int e = 0; e < ENUM; e++) acc[e] = fmaf(xv, w[e], acc[e]);
    }
#pragma unroll
    for (int e = 0; e < ENUM; e++) {
#pragma unroll
        for (int s = 16; s > 0; s >>= 1)
            acc[e] += __shfl_xor_sync(0xffffffffu, acc[e], s);
    }
    if (lane == 0) {
        float v[ENUM];
#pragma unroll
        for (int e = 0; e < ENUM; e++) v[e] = acc[e] + br[e];
        int i0 = 0; float v0 = v[0];
#pragma unroll
        for (int e = 1; e < ENUM; e++) if (v[e] > v0) { v0 = v[e]; i0 = e; }
        int i1 = -1; float v1 = -1e30f;
#pragma unroll
        for (int e = 0; e < ENUM; e++)
            if (e != i0 && v[e] > v1) { v1 = v[e]; i1 = e; }
        float g0 = 1.f / (1.f + expf(v1 - v0));
        float g1 = 1.f - g0;
        int p0 = atomicAdd(&g_counts[i0], 1);
        int p1 = atomicAdd(&g_counts[i1], 1);
        g_e[2 * t]     = i0; g_pos[2 * t]     = p0; g_gate[2 * t]     = g0;
        g_e[2 * t + 1] = i1; g_pos[2 * t + 1] = p1; g_gate[2 * t + 1] = g1;
    }
}

__global__ void offsets_kernel() {
    if (threadIdx.x == 0) {
        int s = 0;
        for (int e = 0; e < ENUM; e++) { g_offsets[e] = s; s += g_counts[e]; }
    }
}

__global__ void build_rows_kernel() {
    int t = blockIdx.x * blockDim.x + threadIdx.x;
    if (t >= TNUM) return;
#pragma unroll
    for (int k = 0; k < 2; k++) {
        int e = g_e[2 * t + k];
        int row = g_offsets[e] + g_pos[2 * t + k];
        g_row_token[row] = t;
        g_token_rows[2 * t + k] = row;
    }
}

// ---------------- grouped GEMM: tf32 mma.sync + 2-stage cp.async (static smem) ----------------
#define BM 128
#define BN 128
#define BK 16
#define SA_STRIDE 20        // floats (16 + 4 pad); 80B row, 16B-multiple
#define SB_STRIDE 136       // floats (128 + 8 pad); 544B row, 16B-multiple
#define A_STAGE_BYTES (BM * SA_STRIDE * 4)            // 10240
#define B_STAGE_BYTES (BK * SB_STRIDE * 4)            // 8704
#define STAGE_BYTES (A_STAGE_BYTES + B_STAGE_BYTES)   // 18944
#define STAGE_FLOATS (STAGE_BYTES / 4)

#define CP_ASYNC16(dst, src) \
    asm volatile("cp.async.cg.shared.global [%0], [%1], 16;" \
                 :: "r"(dst), "l"(src) : "memory")
#define CP_COMMIT() asm volatile("cp.async.commit_group;" ::: "memory")
#define CP_WAIT0()  asm volatile("cp.async.wait_group 0;" ::: "memory")

// PHASE 1: A = g_xr gathered via row->token (K=DDIM), C = g_h (N=HDIM), ReLU+bias+rna
// PHASE 2: A = g_h direct rows (K=HDIM),             C = g_y (N=ODIM), bias
template <int PHASE, int KD, int ND>
__global__ void __launch_bounds__(256, 2) moe_gemm_kernel(
    const float* __restrict__ Bw,      // [E, KD, ND] native layout (harness ptr)
    const float* __restrict__ biasB) { // [E, ND]               (harness ptr)
    int e = blockIdx.z;
    int cnt = g_counts[e];
    int m0 = blockIdx.y * BM;
    if (m0 >= cnt) return;
    int rbase = g_offsets[e] + m0;
    int n0 = blockIdx.x * BN;

    // A operand selected IN DEVICE CODE (do not pass __device__ arrays as args)
    const float* Aglob = (PHASE == 1) ? g_xr : g_h;

    __shared__ __align__(16) float sbuf[2][STAGE_FLOATS];
    __shared__ uint32_t sAoff[BM];

    int tid  = threadIdx.x;
    int lane = tid & 31;
    int warp = tid >> 5;

    if (tid < BM) {
        uint32_t off = 0;
        if (m0 + tid < cnt) {
            int row = rbase + tid;
            off = (PHASE == 1) ? (uint32_t)g_row_token[row] * (uint32_t)KD
                               : (uint32_t)row * (uint32_t)KD;
        }
        sAoff[tid] = off;
    }
    __syncthreads();

    // per-thread cp.async granule mapping: 2 A granules + 2 B granules (16B each)
    uint32_t base0 = smem_u32(&sbuf[0][0]);
    const char* aSrc[2];
    uint32_t    aDst[2];
    const char* bSrc[2];
    uint32_t    bDst[2];
#pragma unroll
    for (int i = 0; i < 2; i++) {
        int idx = tid + 256 * i;        // A granule id 0..511
        int row = idx >> 2;             // 0..127
        int gg  = idx & 3;              // 16B granule within 64B row
        aSrc[i] = (const char*)Aglob + (size_t)sAoff[row] * 4 + gg * 16;
        aDst[i] = (uint32_t)(row * (SA_STRIDE * 4) + gg * 16);
    }
#pragma unroll
    for (int i = 0; i < 2; i++) {
        int idx = tid + 256 * i;        // B granule id 0..511
        int row = idx >> 5;             // k row 0..15
        int gg  = idx & 31;             // 16B granule within 512B row
        bSrc[i] = (const char*)Bw + (((size_t)e * KD + row) * ND + n0) * 4 + gg * 16;
        bDst[i] = (uint32_t)(A_STAGE_BYTES + row * (SB_STRIDE * 4) + gg * 16);
    }

    const int NK = KD / BK;

    // prologue: stage 0 into buffer 0
#pragma unroll
    for (int i = 0; i < 2; i++) {
        CP_ASYNC16(base0 + aDst[i], aSrc[i]);
        CP_ASYNC16(base0 + bDst[i], bSrc[i]);
    }
    CP_COMMIT();

    // warp tile mapping (verified in R1)
    int wm = (warp >> 2) * 64;
    int wn = (warp & 3) * 32;
    int g  = lane >> 2;
    int tg = lane & 3;

    float acc[4][4][4];
#pragma unroll
    for (int i = 0; i < 4; i++)
#pragma unroll
        for (int j = 0; j < 4; j++)
#pragma unroll
            for (int r = 0; r < 4; r++) acc[i][j][r] = 0.f;

    for (int kt = 0; kt < NK; kt++) {
        CP_WAIT0();          // stage kt fully landed
        __syncthreads();     // visible to all; prior reads of other buffer done

        // issue stage kt+1 into the other buffer (overlaps compute below)
        if (kt + 1 < NK) {
            uint32_t sb = base0 + ((kt + 1) & 1) * STAGE_BYTES;
            size_t aAdv = (size_t)(kt + 1) * (BK * 4);
            size_t bAdv = (size_t)(kt + 1) * (BK * (size_t)ND * 4);
#pragma unroll
            for (int i = 0; i < 2; i++) {
                CP_ASYNC16(sb + aDst[i], aSrc[i] + aAdv);
                CP_ASYNC16(sb + bDst[i], bSrc[i] + bAdv);
            }
            CP_COMMIT();
        }

        const float* sA = &sbuf[kt & 1][0];
        const float* sB = &sbuf[kt & 1][A_STAGE_BYTES / 4];

#pragma unroll
        for (int ks = 0; ks < 2; ks++) {
            int kk = ks * 8;
            uint32_t af[4][4];
#pragma unroll
            for (int i = 0; i < 4; i++) {
                int mrow = wm + i * 16;
                af[i][0] = __float_as_uint(sA[(mrow + g) * SA_STRIDE + kk + tg]);
                af[i][1] = __float_as_uint(sA[(mrow + g + 8) * SA_STRIDE + kk + tg]);
                af[i][2] = __float_as_uint(sA[(mrow + g) * SA_STRIDE + kk + tg + 4]);
                af[i][3] = __float_as_uint(sA[(mrow + g + 8) * SA_STRIDE + kk + tg + 4]);
            }
            uint32_t bf[4][2];
#pragma unroll
            for (int j = 0; j < 4; j++) {
                int nc = wn + j * 8 + g;
                bf[j][0] = rna_tf32_u(sB[(kk + tg) * SB_STRIDE + nc]);
                bf[j][1] = rna_tf32_u(sB[(kk + tg + 4) * SB_STRIDE + nc]);
            }
#pragma unroll
            for (int i = 0; i < 4; i++)
#pragma unroll
                for (int j = 0; j < 4; j++) {
                    asm volatile(
                        "mma.sync.aligned.m16n8k8.row.col.f32.tf32.tf32.f32 "
                        "{%0,%1,%2,%3}, {%4,%5,%6,%7}, {%8,%9}, {%0,%1,%2,%3};\n"
                        : "+f"(acc[i][j][0]), "+f"(acc[i][j][1]),
                          "+f"(acc[i][j][2]), "+f"(acc[i][j][3])
                        : "r"(af[i][0]), "r"(af[i][1]), "r"(af[i][2]), "r"(af[i][3]),
                          "r"(bf[j][0]), "r"(bf[j][1]));
                }
        }
    }

    // epilogue: bias (+ReLU+rna for phase1), masked rows
    const float* bias = biasB + (size_t)e * ND + n0;
    float* Cbase = (PHASE == 1) ? g_h : g_y;
#pragma unroll
    for (int i = 0; i < 4; i++) {
#pragma unroll
        for (int half = 0; half < 2; half++) {
            int ml = wm + i * 16 + g + half * 8;
            if (m0 + ml < cnt) {
                float* crow = Cbase + (size_t)(rbase + ml) * ND + n0;
#pragma unroll
                for (int j = 0; j < 4; j++) {
                    int nc = wn + j * 8 + tg * 2;
                    float c0 = acc[i][j][half * 2 + 0] + bias[nc];
                    float c1 = acc[i][j][half * 2 + 1] + bias[nc + 1];
                    if (PHASE == 1) {
                        c0 = rna_tf32(fmaxf(c0, 0.f));
                        c1 = rna_tf32(fmaxf(c1, 0.f));
                    }
                    float2 v; v.x = c0; v.y = c1;
                    *(float2*)(crow + nc) = v;
                }
            }
        }
    }
}

// ---------------- gated combine ----------------
__global__ void combine_kernel(float* __restrict__ out) {
    int idx = blockIdx.x * blockDim.x + threadIdx.x;
    int t = idx >> 8;
    int c = (idx & 255) * 4;
    int r0 = g_token_rows[2 * t];
    int r1 = g_token_rows[2 * t + 1];
    float w0 = g_gate[2 * t];
    float w1 = g_gate[2 * t + 1];
    float4 a = *(const float4*)(g_y + (size_t)r0 * ODIM + c);
    float4 b = *(const float4*)(g_y + (size_t)r1 * ODIM + c);
    float4 o;
    o.x = w0 * a.x + w1 * b.x;
    o.y = w0 * a.y + w1 * b.y;
    o.z = w0 * a.z + w1 * b.z;
    o.w = w0 * a.w + w1 * b.w;
    *(float4*)(out + (size_t)t * ODIM + c) = o;
}

// ---------------- launch ----------------
extern "C" void kernel_launch(void* const* d_in, const int* in_sizes, int n_in,
                              void* d_out, int out_size) {
    const float* x  = (const float*)d_in[0];
    const float* Wr = (const float*)d_in[1];
    const float* br = (const float*)d_in[2];
    const float* W1 = (const float*)d_in[3];
    const float* b1 = (const float*)d_in[4];
    const float* W2 = (const float*)d_in[5];
    const float* b2 = (const float*)d_in[6];
    float* out = (float*)d_out;

    round_x_kernel<<<(TNUM * DDIM / 4) / 256, 256>>>(x);

    zero_counts_kernel<<<1, 32>>>();
    router_kernel<<<TNUM / 8, 256>>>(x, Wr, br);
    offsets_kernel<<<1, 32>>>();
    build_rows_kernel<<<TNUM / 256, 256>>>();

    dim3 g1(HDIM / BN, TNUM / BM, ENUM);   // (32, 32, 8), most m-tiles early-exit
    moe_gemm_kernel<1, DDIM, HDIM><<<g1, 256>>>(W1, b1);

    dim3 g2(ODIM / BN, TNUM / BM, ENUM);   // (8, 32, 8)
    moe_gemm_kernel<2, HDIM, ODIM><<<g2, 256>>>(W2, b2);

    combine_kernel<<<TNUM, 256>>>(out);
}

// round 6
// speedup vs baseline: 1.9963x; 1.1411x over previous
#include <cuda_runtime.h>
#include <cstdint>
#include <math.h>

// Problem dims (fixed by setup_inputs)
#define TNUM 4096
#define DDIM 1024
#define HDIM 4096
#define ODIM 1024
#define ENUM 8
#define NROWS (TNUM * 2)

// ---------------- scratch (static __device__, no allocs) ----------------
// ONLY referenced from device code (host-side use passes shadow symbol!)
__device__ int   g_counts[ENUM];
__device__ int   g_offsets[ENUM];
__device__ int   g_e[NROWS];
__device__ int   g_pos[NROWS];
__device__ float g_gate[NROWS];
__device__ int   g_row_token[NROWS];
__device__ int   g_token_rows[NROWS];
__device__ float g_xr[(size_t)TNUM * DDIM];   // x rounded to tf32 (16 MB)
__device__ float g_h[(size_t)NROWS * HDIM];   // tf32-rounded intermediate (128 MB)
__device__ float g_y[(size_t)NROWS * ODIM];   // expert outputs (32 MB)

__device__ __forceinline__ float rna_tf32(float f) {
    uint32_t u;
    asm("cvt.rna.tf32.f32 %0, %1;" : "=r"(u) : "f"(f));
    return __uint_as_float(u);
}
__device__ __forceinline__ uint32_t rna_tf32_u(float f) {
    uint32_t u;
    asm("cvt.rna.tf32.f32 %0, %1;" : "=r"(u) : "f"(f));
    return u;
}
__device__ __forceinline__ uint32_t smem_u32(const void* p) {
    uint32_t a;
    asm("{ .reg .u64 t; cvta.to.shared.u64 t, %1; cvt.u32.u64 %0, t; }" : "=r"(a) : "l"(p));
    return a;
}

// ---------------- prep: rounded x ----------------
__global__ void round_x_kernel(const float* __restrict__ x) {
    int i = blockIdx.x * blockDim.x + threadIdx.x;
    float4 v = *(const float4*)(x + (size_t)i * 4);
    v.x = rna_tf32(v.x); v.y = rna_tf32(v.y); v.z = rna_tf32(v.z); v.w = rna_tf32(v.w);
    *(float4*)(g_xr + (size_t)i * 4) = v;
}

// ---------------- router ----------------
__global__ void zero_counts_kernel() {
    if (threadIdx.x < ENUM) g_counts[threadIdx.x] = 0;
}

__global__ void router_kernel(const float* __restrict__ x,
                              const float* __restrict__ Wr,
                              const float* __restrict__ br) {
    int warp = threadIdx.x >> 5;
    int lane = threadIdx.x & 31;
    int t = blockIdx.x * 8 + warp;
    if (t >= TNUM) return;
    const float* xr = x + (size_t)t * DDIM;
    float acc[ENUM];
#pragma unroll
    for (int e = 0; e < ENUM; e++) acc[e] = 0.f;
    for (int d = lane; d < DDIM; d += 32) {
        float xv = xr[d];
        const float* w = Wr + (size_t)d * ENUM;
#pragma unroll
        for (int e = 0; e < ENUM; e++) acc[e] = fmaf(xv, w[e], acc[e]);
    }
#pragma unroll
    for (int e = 0; e < ENUM; e++) {
#pragma unroll
        for (int s = 16; s > 0; s >>= 1)
            acc[e] += __shfl_xor_sync(0xffffffffu, acc[e], s);
    }
    if (lane == 0) {
        float v[ENUM];
#pragma unroll
        for (int e = 0; e < ENUM; e++) v[e] = acc[e] + br[e];
        int i0 = 0; float v0 = v[0];
#pragma unroll
        for (int e = 1; e < ENUM; e++) if (v[e] > v0) { v0 = v[e]; i0 = e; }
        int i1 = -1; float v1 = -1e30f;
#pragma unroll
        for (int e = 0; e < ENUM; e++)
            if (e != i0 && v[e] > v1) { v1 = v[e]; i1 = e; }
        float g0 = 1.f / (1.f + expf(v1 - v0));
        float g1 = 1.f - g0;
        int p0 = atomicAdd(&g_counts[i0], 1);
        int p1 = atomicAdd(&g_counts[i1], 1);
        g_e[2 * t]     = i0; g_pos[2 * t]     = p0; g_gate[2 * t]     = g0;
        g_e[2 * t + 1] = i1; g_pos[2 * t + 1] = p1; g_gate[2 * t + 1] = g1;
    }
}

__global__ void offsets_kernel() {
    if (threadIdx.x == 0) {
        int s = 0;
        for (int e = 0; e < ENUM; e++) { g_offsets[e] = s; s += g_counts[e]; }
    }
}

__global__ void build_rows_kernel() {
    int t = blockIdx.x * blockDim.x + threadIdx.x;
    if (t >= TNUM) return;
#pragma unroll
    for (int k = 0; k < 2; k++) {
        int e = g_e[2 * t + k];
        int row = g_offsets[e] + g_pos[2 * t + k];
        g_row_token[row] = t;
        g_token_rows[2 * t + k] = row;
    }
}

// ------ grouped GEMM: tf32 mma.sync, BK=32, 3-stage cp.async (dyn smem) ------
#define BM 128
#define BN 128
#define BK 32
#define SA_STRIDE 36        // floats (32 + 4 pad); conflict-free (R1-verified)
#define SB_STRIDE 136       // floats (128 + 8 pad); conflict-free (R1-verified)
#define A_STAGE_BYTES (BM * SA_STRIDE * 4)            // 18432
#define B_STAGE_BYTES (BK * SB_STRIDE * 4)            // 17408
#define STAGE_BYTES (A_STAGE_BYTES + B_STAGE_BYTES)   // 35840
#define NSTAGE 3
#define DYN_SMEM (NSTAGE * STAGE_BYTES)               // 107520

#define CP_ASYNC16(dst, src) \
    asm volatile("cp.async.cg.shared.global [%0], [%1], 16;" \
                 :: "r"(dst), "l"(src) : "memory")
#define CP_COMMIT() asm volatile("cp.async.commit_group;" ::: "memory")
#define CP_WAIT1()  asm volatile("cp.async.wait_group 1;" ::: "memory")

// PHASE 1: A = g_xr gathered via row->token (K=DDIM), C = g_h, ReLU+bias+rna
// PHASE 2: A = g_h direct rows (K=HDIM),             C = g_y, bias
template <int PHASE, int KD, int ND>
__global__ void __launch_bounds__(256, 2) moe_gemm_kernel(
    const float* __restrict__ Bw,      // [E, KD, ND] (harness ptr)
    const float* __restrict__ biasB) { // [E, ND]     (harness ptr)
    int e = blockIdx.z;
    int cnt = g_counts[e];
    int m0 = blockIdx.y * BM;
    if (m0 >= cnt) return;
    int rbase = g_offsets[e] + m0;
    int n0 = blockIdx.x * BN;

    const float* Aglob = (PHASE == 1) ? g_xr : g_h;   // device-side select

    extern __shared__ __align__(16) char dynsmem[];
    __shared__ uint32_t sAoff[BM];

    int tid  = threadIdx.x;
    int lane = tid & 31;
    int warp = tid >> 5;

    if (tid < BM) {
        uint32_t off = 0;
        if (m0 + tid < cnt) {
            int row = rbase + tid;
            off = (PHASE == 1) ? (uint32_t)g_row_token[row] * (uint32_t)KD
                               : (uint32_t)row * (uint32_t)KD;
        }
        sAoff[tid] = off;
    }
    __syncthreads();

    // per-thread cp.async mapping: 4 A granules + 4 B granules (16B each)
    uint32_t base0 = smem_u32(dynsmem);
    const char* aSrc[4];
    uint32_t    aDst[4];
    const char* bSrc[4];
    uint32_t    bDst[4];
#pragma unroll
    for (int i = 0; i < 4; i++) {
        int idx = tid + 256 * i;        // A granule id 0..1023
        int row = idx >> 3;             // 0..127
        int gg  = idx & 7;              // 16B granule within 128B row
        aSrc[i] = (const char*)Aglob + (size_t)sAoff[row] * 4 + gg * 16;
        aDst[i] = (uint32_t)(row * (SA_STRIDE * 4) + gg * 16);
    }
#pragma unroll
    for (int i = 0; i < 4; i++) {
        int idx = tid + 256 * i;        // B granule id 0..1023
        int row = idx >> 5;             // k row 0..31
        int gg  = idx & 31;             // 16B granule within 512B row
        bSrc[i] = (const char*)Bw + (((size_t)e * KD + row) * ND + n0) * 4 + gg * 16;
        bDst[i] = (uint32_t)(A_STAGE_BYTES + row * (SB_STRIDE * 4) + gg * 16);
    }

    const int NK = KD / BK;

    // prologue: stages 0 and 1
#pragma unroll
    for (int s = 0; s < 2; s++) {
        uint32_t sb = base0 + s * STAGE_BYTES;
        size_t aAdv = (size_t)s * (BK * 4);
        size_t bAdv = (size_t)s * (BK * (size_t)ND * 4);
#pragma unroll
        for (int i = 0; i < 4; i++) {
            CP_ASYNC16(sb + aDst[i], aSrc[i] + aAdv);
            CP_ASYNC16(sb + bDst[i], bSrc[i] + bAdv);
        }
        CP_COMMIT();
    }

    int wm = (warp >> 2) * 64;
    int wn = (warp & 3) * 32;
    int g  = lane >> 2;
    int tg = lane & 3;

    float acc[4][4][4];
#pragma unroll
    for (int i = 0; i < 4; i++)
#pragma unroll
        for (int j = 0; j < 4; j++)
#pragma unroll
            for (int r = 0; r < 4; r++) acc[i][j][r] = 0.f;

    for (int kt = 0; kt < NK; kt++) {
        CP_WAIT1();          // groups ≤ kt+1 outstanding-1 → stage kt landed
        __syncthreads();     // buffer (kt+2)%3 reads (iter kt-1) finished

        // issue stage kt+2 into buffer (kt+2)%3; commit EVERY iter (group math)
        int kn = kt + 2;
        if (kn < NK) {
            uint32_t sb = base0 + (kn % NSTAGE) * STAGE_BYTES;
            size_t aAdv = (size_t)kn * (BK * 4);
            size_t bAdv = (size_t)kn * (BK * (size_t)ND * 4);
#pragma unroll
            for (int i = 0; i < 4; i++) {
                CP_ASYNC16(sb + aDst[i], aSrc[i] + aAdv);
                CP_ASYNC16(sb + bDst[i], bSrc[i] + bAdv);
            }
        }
        CP_COMMIT();

        const float* sA = (const float*)(dynsmem + (kt % NSTAGE) * STAGE_BYTES);
        const float* sB = (const float*)(dynsmem + (kt % NSTAGE) * STAGE_BYTES + A_STAGE_BYTES);

#pragma unroll
        for (int ks = 0; ks < 4; ks++) {
            int kk = ks * 8;
            uint32_t af[4][4];
#pragma unroll
            for (int i = 0; i < 4; i++) {
                int mrow = wm + i * 16;
                af[i][0] = __float_as_uint(sA[(mrow + g) * SA_STRIDE + kk + tg]);
                af[i][1] = __float_as_uint(sA[(mrow + g + 8) * SA_STRIDE + kk + tg]);
                af[i][2] = __float_as_uint(sA[(mrow + g) * SA_STRIDE + kk + tg + 4]);
                af[i][3] = __float_as_uint(sA[(mrow + g + 8) * SA_STRIDE + kk + tg + 4]);
            }
            uint32_t bf[4][2];
#pragma unroll
            for (int j = 0; j < 4; j++) {
                int nc = wn + j * 8 + g;
                bf[j][0] = rna_tf32_u(sB[(kk + tg) * SB_STRIDE + nc]);
                bf[j][1] = rna_tf32_u(sB[(kk + tg + 4) * SB_STRIDE + nc]);
            }
#pragma unroll
            for (int i = 0; i < 4; i++)
#pragma unroll
                for (int j = 0; j < 4; j++) {
                    asm volatile(
                        "mma.sync.aligned.m16n8k8.row.col.f32.tf32.tf32.f32 "
                        "{%0,%1,%2,%3}, {%4,%5,%6,%7}, {%8,%9}, {%0,%1,%2,%3};\n"
                        : "+f"(acc[i][j][0]), "+f"(acc[i][j][1]),
                          "+f"(acc[i][j][2]), "+f"(acc[i][j][3])
                        : "r"(af[i][0]), "r"(af[i][1]), "r"(af[i][2]), "r"(af[i][3]),
                          "r"(bf[j][0]), "r"(bf[j][1]));
                }
        }
    }

    // epilogue
    const float* bias = biasB + (size_t)e * ND + n0;
    float* Cbase = (PHASE == 1) ? g_h : g_y;
#pragma unroll
    for (int i = 0; i < 4; i++) {
#pragma unroll
        for (int half = 0; half < 2; half++) {
            int ml = wm + i * 16 + g + half * 8;
            if (m0 + ml < cnt) {
                float* crow = Cbase + (size_t)(rbase + ml) * ND + n0;
#pragma unroll
                for (int j = 0; j < 4; j++) {
                    int nc = wn + j * 8 + tg * 2;
                    float c0 = acc[i][j][half * 2 + 0] + bias[nc];
                    float c1 = acc[i][j][half * 2 + 1] + bias[nc + 1];
                    if (PHASE == 1) {
                        c0 = rna_tf32(fmaxf(c0, 0.f));
                        c1 = rna_tf32(fmaxf(c1, 0.f));
                    }
                    float2 v; v.x = c0; v.y = c1;
                    *(float2*)(crow + nc) = v;
                }
            }
        }
    }
}

// ---------------- gated combine ----------------
__global__ void combine_kernel(float* __restrict__ out) {
    int idx = blockIdx.x * blockDim.x + threadIdx.x;
    int t = idx >> 8;
    int c = (idx & 255) * 4;
    int r0 = g_token_rows[2 * t];
    int r1 = g_token_rows[2 * t + 1];
    float w0 = g_gate[2 * t];
    float w1 = g_gate[2 * t + 1];
    float4 a = *(const float4*)(g_y + (size_t)r0 * ODIM + c);
    float4 b = *(const float4*)(g_y + (size_t)r1 * ODIM + c);
    float4 o;
    o.x = w0 * a.x + w1 * b.x;
    o.y = w0 * a.y + w1 * b.y;
    o.z = w0 * a.z + w1 * b.z;
    o.w = w0 * a.w + w1 * b.w;
    *(float4*)(out + (size_t)t * ODIM + c) = o;
}

// ---------------- launch ----------------
extern "C" void kernel_launch(void* const* d_in, const int* in_sizes, int n_in,
                              void* d_out, int out_size) {
    const float* x  = (const float*)d_in[0];
    const float* Wr = (const float*)d_in[1];
    const float* br = (const float*)d_in[2];
    const float* W1 = (const float*)d_in[3];
    const float* b1 = (const float*)d_in[4];
    const float* W2 = (const float*)d_in[5];
    const float* b2 = (const float*)d_in[6];
    float* out = (float*)d_out;

    cudaFuncSetAttribute(moe_gemm_kernel<1, DDIM, HDIM>,
                         cudaFuncAttributeMaxDynamicSharedMemorySize, DYN_SMEM);
    cudaFuncSetAttribute(moe_gemm_kernel<2, HDIM, ODIM>,
                         cudaFuncAttributeMaxDynamicSharedMemorySize, DYN_SMEM);

    round_x_kernel<<<(TNUM * DDIM / 4) / 256, 256>>>(x);

    zero_counts_kernel<<<1, 32>>>();
    router_kernel<<<TNUM / 8, 256>>>(x, Wr, br);
    offsets_kernel<<<1, 32>>>();
    build_rows_kernel<<<TNUM / 256, 256>>>();

    dim3 g1(HDIM / BN, TNUM / BM, ENUM);   // (32, 32, 8)
    moe_gemm_kernel<1, DDIM, HDIM><<<g1, 256, DYN_SMEM>>>(W1, b1);

    dim3 g2(ODIM / BN, TNUM / BM, ENUM);   // (8, 32, 8)
    moe_gemm_kernel<2, HDIM, ODIM><<<g2, 256, DYN_SMEM>>>(W2, b2);

    combine_kernel<<<TNUM, 256>>>(out);
}